// round 1
// baseline (speedup 1.0000x reference)
#include <cuda_runtime.h>
#include <math.h>
#include <stdint.h>

// ---------------------------------------------------------------------------
// Problem constants
// ---------------------------------------------------------------------------
#define BB        2
#define LL        2048
#define DD        1024
#define HH        16
#define PP        8        // phases per head
#define NPH       128      // total phases
#define HD        64       // head dim
#define ROWS      (BB*LL)  // 4096

// softmax constants: score_raw in [-8,8]; p = exp2(s_raw*QA - QB)
// QA = SCALE*log2(e), QB = 8*SCALE*log2(e), SCALE = 1/sqrt(8)
__device__ __forceinline__ float qa_const() {
    return (float)(0.35355339059327376 * 1.4426950408889634);
}
__device__ __forceinline__ float qb_const() {
    return (float)(8.0 * 0.35355339059327376 * 1.4426950408889634);
}

// ---------------------------------------------------------------------------
// f32x2 packed helpers (sm_100+)
// ---------------------------------------------------------------------------
__device__ __forceinline__ unsigned long long pk2(float lo, float hi) {
    unsigned long long r;
    asm("mov.b64 %0, {%1, %2};" : "=l"(r) : "f"(lo), "f"(hi));
    return r;
}
__device__ __forceinline__ float2 up2(unsigned long long v) {
    float2 r;
    asm("mov.b64 {%0, %1}, %2;" : "=f"(r.x), "=f"(r.y) : "l"(v));
    return r;
}
#define FMA2(d, a, b) asm("fma.rn.f32x2 %0, %1, %2, %0;" : "+l"(d) : "l"(a), "l"(b))

// ---------------------------------------------------------------------------
// Scratch (device globals; no allocation allowed)
// ---------------------------------------------------------------------------
static __device__ float g_phq[ROWS * NPH];       // Q phases  (row-major, 4096x128)
static __device__ float g_phk[ROWS * NPH];       // K phases
static __device__ float g_qf [BB * HH * LL * 16];// Q features (bh, l, 16)
static __device__ float g_kf [BB * HH * LL * 16];// K features
static __device__ float g_v  [ROWS * DD];        // V = x_real @ Wv^T   (b*l, d)
static __device__ float g_ao [ROWS * DD];        // attention output    (b*l, d)
static __device__ float g_pj [ROWS * DD];        // ao @ Wo^T           (b*l, d)

// ---------------------------------------------------------------------------
// SGEMM: C[M,N] = A[M,K] * B[N,K]^T  (all row-major). 128x128 tile, 256 thr,
// 8x8 per thread, K-tile 8. blockIdx.z selects (B0,C0) or (B1,C1) so two
// GEMMs sharing A can run in one launch (used for the Q/K phase projections).
// ---------------------------------------------------------------------------
__global__ __launch_bounds__(256) void sgemm_abt(
    const float* __restrict__ A, const float* __restrict__ B0,
    const float* __restrict__ B1, float* __restrict__ C0, float* __restrict__ C1,
    int M, int N, int K)
{
    const float* Bm = blockIdx.z ? B1 : B0;
    float* C = blockIdx.z ? C1 : C0;

    __shared__ __align__(16) float As[8][132];
    __shared__ __align__(16) float Bs[8][132];

    const int t  = threadIdx.x;
    const int tx = t & 15, ty = t >> 4;
    const int rowBase = blockIdx.y * 128;
    const int colBase = blockIdx.x * 128;
    const int lr = t >> 1;
    const int lk = (t & 1) * 4;

    const float* Ap = A  + (size_t)(rowBase + lr) * K + lk;
    const float* Bp = Bm + (size_t)(colBase + lr) * K + lk;

    unsigned long long c2[8][4];
#pragma unroll
    for (int i = 0; i < 8; i++)
#pragma unroll
        for (int j = 0; j < 4; j++) c2[i][j] = 0ULL;

    for (int k0 = 0; k0 < K; k0 += 8) {
        float4 av = *(const float4*)(Ap + k0);
        float4 bv = *(const float4*)(Bp + k0);
        __syncthreads();
        As[lk + 0][lr] = av.x; As[lk + 1][lr] = av.y;
        As[lk + 2][lr] = av.z; As[lk + 3][lr] = av.w;
        Bs[lk + 0][lr] = bv.x; Bs[lk + 1][lr] = bv.y;
        Bs[lk + 2][lr] = bv.z; Bs[lk + 3][lr] = bv.w;
        __syncthreads();
#pragma unroll
        for (int k = 0; k < 8; k++) {
            float4 a0 = *(const float4*)&As[k][ty * 8];
            float4 a1 = *(const float4*)&As[k][ty * 8 + 4];
            const unsigned long long* br =
                (const unsigned long long*)&Bs[k][tx * 8];
            unsigned long long b2_0 = br[0], b2_1 = br[1];
            unsigned long long b2_2 = br[2], b2_3 = br[3];
            float a[8] = {a0.x, a0.y, a0.z, a0.w, a1.x, a1.y, a1.z, a1.w};
#pragma unroll
            for (int i = 0; i < 8; i++) {
                unsigned long long ad = pk2(a[i], a[i]);
                FMA2(c2[i][0], ad, b2_0);
                FMA2(c2[i][1], ad, b2_1);
                FMA2(c2[i][2], ad, b2_2);
                FMA2(c2[i][3], ad, b2_3);
            }
        }
    }

#pragma unroll
    for (int i = 0; i < 8; i++) {
        float2 v0 = up2(c2[i][0]), v1 = up2(c2[i][1]);
        float2 v2 = up2(c2[i][2]), v3 = up2(c2[i][3]);
        size_t off = (size_t)(rowBase + ty * 8 + i) * N + colBase + tx * 8;
        *(float4*)&C[off]     = make_float4(v0.x, v0.y, v1.x, v1.y);
        *(float4*)&C[off + 4] = make_float4(v2.x, v2.y, v3.x, v3.y);
    }
}

// ---------------------------------------------------------------------------
// Features: phase -> (cos, sin) with bias + positional phase, transposed into
// (b, h, l, 16) layout used by the attention kernel.
// ---------------------------------------------------------------------------
__global__ void feat_kernel(const float* __restrict__ phq,
                            const float* __restrict__ phk,
                            const float* __restrict__ bq,
                            const float* __restrict__ bk,
                            float* __restrict__ qfo, float* __restrict__ kfo)
{
    int idx = blockIdx.x * blockDim.x + threadIdx.x;
    if (idx >= ROWS * NPH) return;
    int p   = idx & (NPH - 1);
    int row = idx >> 7;                 // b*L + l
    int l   = row & (LL - 1);
    int b   = row >> 11;
    int h   = p >> 3;
    int pp  = p & 7;
    int k2  = p & ~1;

    // invfreq = 10000^(-k2/128) = 2^(-k2 * log2(10000)/128)
    const float LC = (float)(13.287712379549449 / 128.0);
    float invf = exp2f(-(float)k2 * LC);
    float pos  = (float)l * invf;

    size_t ob = (((size_t)b * HH + h) * LL + l) * 16 + pp;
    float s, c;
    sincosf(phq[idx] + bq[p] + pos, &s, &c);
    qfo[ob] = c; qfo[ob + 8] = s;
    sincosf(phk[idx] + bk[p] + pos, &s, &c);
    kfo[ob] = c; kfo[ob + 8] = s;
}

// ---------------------------------------------------------------------------
// Attention: scores bounded by sqrt(8) -> fixed-max softmax, single pass.
// grid (B*H = 32, 8); each block handles the complementary query-tile pair
// (y, 15-y) -> uniform 34 key tiles per block. 128 threads, 1 query row each.
// ---------------------------------------------------------------------------
__global__ __launch_bounds__(128) void attn_kernel(
    const float* __restrict__ qf, const float* __restrict__ kf,
    const float* __restrict__ V, float* __restrict__ Out)
{
    __shared__ __align__(16) float kfs[64 * 16];
    __shared__ __align__(16) float vs[64 * 64];

    const int bh  = blockIdx.x;
    const int b   = bh >> 4;
    const int h   = bh & 15;
    const int tid = threadIdx.x;
    const float QA = qa_const();
    const float QB = qb_const();

#pragma unroll 1
    for (int part = 0; part < 2; part++) {
        const int qt   = part ? (15 - (int)blockIdx.y) : (int)blockIdx.y;
        const int qrow = qt * 128 + tid;

        const unsigned long long* qp =
            (const unsigned long long*)(qf + ((size_t)bh * LL + qrow) * 16);
        unsigned long long qd[8];
#pragma unroll
        for (int i = 0; i < 8; i++) qd[i] = qp[i];

        unsigned long long o2[32];
#pragma unroll
        for (int i = 0; i < 32; i++) o2[i] = 0ULL;
        float lsum = 0.f;

        const int ntiles = qt * 2 + 2;
        for (int kt = 0; kt < ntiles; kt++) {
            const int c0 = kt * 64;
            __syncthreads();
            { // K-feature tile: 64 x 16 floats
                const float4* src =
                    (const float4*)(kf + ((size_t)bh * LL + c0) * 16);
                float4* dst = (float4*)kfs;
                dst[tid]       = src[tid];
                dst[tid + 128] = src[tid + 128];
            }
            { // V tile: 64 x 64 floats
                const float* vb = V + ((size_t)b * LL + c0) * DD + h * HD;
                float4* dst = (float4*)vs;
#pragma unroll
                for (int r = 0; r < 8; r++) {
                    int f  = tid + r * 128;
                    int j  = f >> 4;
                    int d4 = f & 15;
                    dst[f] = *(const float4*)(vb + (size_t)j * DD + (d4 << 2));
                }
            }
            __syncthreads();

            const int jmax = min(63, qrow - c0);
            for (int j = 0; j <= jmax; j++) {
                const unsigned long long* kp =
                    (const unsigned long long*)(kfs + (j << 4));
                unsigned long long acc = 0ULL;
#pragma unroll
                for (int c = 0; c < 8; c++) FMA2(acc, qd[c], kp[c]);
                float2 av = up2(acc);
                float s = av.x + av.y;
                float p = exp2f(fmaf(s, QA, -QB));
                lsum += p;
                unsigned long long p2 = pk2(p, p);
                const unsigned long long* vr =
                    (const unsigned long long*)(vs + (j << 6));
#pragma unroll
                for (int d = 0; d < 32; d++) FMA2(o2[d], p2, vr[d]);
            }
        }

        const float inv = 1.0f / lsum;
        float* op = Out + ((size_t)b * LL + qrow) * DD + (h << 6);
#pragma unroll
        for (int d4 = 0; d4 < 16; d4++) {
            float2 x0 = up2(o2[2 * d4]);
            float2 x1 = up2(o2[2 * d4 + 1]);
            *(float4*)(op + (d4 << 2)) =
                make_float4(x0.x * inv, x0.y * inv, x1.x * inv, x1.y * inv);
        }
    }
}

// ---------------------------------------------------------------------------
// Residual + LayerNorm. One block per row (1024 elems), 256 threads x float4.
// ---------------------------------------------------------------------------
__global__ __launch_bounds__(256) void ln_kernel(
    const float* __restrict__ xr, const float* __restrict__ pj,
    const float* __restrict__ gamma, const float* __restrict__ beta,
    float* __restrict__ out)
{
    __shared__ float rs[8], rss[8];
    const int row = blockIdx.x;
    const int t   = threadIdx.x;

    const float4* xv = (const float4*)(xr + (size_t)row * DD);
    const float4* pv = (const float4*)(pj + (size_t)row * DD);
    float4 a = xv[t], c = pv[t];
    float h0 = a.x + c.x, h1 = a.y + c.y, h2 = a.z + c.z, h3 = a.w + c.w;
    float s  = h0 + h1 + h2 + h3;
    float ss = h0 * h0 + h1 * h1 + h2 * h2 + h3 * h3;
#pragma unroll
    for (int o = 16; o > 0; o >>= 1) {
        s  += __shfl_down_sync(0xffffffffu, s,  o);
        ss += __shfl_down_sync(0xffffffffu, ss, o);
    }
    if ((t & 31) == 0) { rs[t >> 5] = s; rss[t >> 5] = ss; }
    __syncthreads();
    float st = 0.f, sst = 0.f;
#pragma unroll
    for (int w = 0; w < 8; w++) { st += rs[w]; sst += rss[w]; }
    const float mu  = st * (1.0f / DD);
    const float var = sst * (1.0f / DD) - mu * mu;
    const float inv = rsqrtf(var + 1e-5f);

    float4 g  = ((const float4*)gamma)[t];
    float4 be = ((const float4*)beta)[t];
    float4 o4 = make_float4((h0 - mu) * inv * g.x + be.x,
                            (h1 - mu) * inv * g.y + be.y,
                            (h2 - mu) * inv * g.z + be.z,
                            (h3 - mu) * inv * g.w + be.w);
    ((float4*)(out + (size_t)row * DD))[t] = o4;
}

// ---------------------------------------------------------------------------
// Launch
// ---------------------------------------------------------------------------
extern "C" void kernel_launch(void* const* d_in, const int* in_sizes, int n_in,
                              void* d_out, int out_size)
{
    const float* x_real = (const float*)d_in[0];
    const float* x_imag = (const float*)d_in[1];
    const float* Wq     = (const float*)d_in[2];
    const float* bq     = (const float*)d_in[3];
    const float* Wk     = (const float*)d_in[4];
    const float* bk     = (const float*)d_in[5];
    const float* Wv     = (const float*)d_in[6];
    const float* Wo     = (const float*)d_in[7];
    const float* gamma  = (const float*)d_in[8];
    const float* beta   = (const float*)d_in[9];
    float* out = (float*)d_out;

    float *phq, *phk, *qfb, *kfb, *vb, *aob, *pjb;
    cudaGetSymbolAddress((void**)&phq, g_phq);
    cudaGetSymbolAddress((void**)&phk, g_phk);
    cudaGetSymbolAddress((void**)&qfb, g_qf);
    cudaGetSymbolAddress((void**)&kfb, g_kf);
    cudaGetSymbolAddress((void**)&vb,  g_v);
    cudaGetSymbolAddress((void**)&aob, g_ao);
    cudaGetSymbolAddress((void**)&pjb, g_pj);

    // 1) Q/K phase projections (shared A = x_imag), packed in one launch
    sgemm_abt<<<dim3(1, 32, 2), 256>>>(x_imag, Wq, Wk, phq, phk,
                                       ROWS, NPH, DD);
    // 2) cos/sin features with bias + positional phase
    feat_kernel<<<(ROWS * NPH) / 256, 256>>>(phq, phk, bq, bk, qfb, kfb);
    // 3) V projection
    sgemm_abt<<<dim3(8, 32, 1), 256>>>(x_real, Wv, Wv, vb, vb,
                                       ROWS, DD, DD);
    // 4) causal interference attention
    attn_kernel<<<dim3(BB * HH, 8), 128>>>(qfb, kfb, vb, aob);
    // 5) output projection
    sgemm_abt<<<dim3(8, 32, 1), 256>>>(aob, Wo, Wo, pjb, pjb,
                                       ROWS, DD, DD);
    // 6) residual + LayerNorm -> first half of output
    ln_kernel<<<ROWS, 256>>>(x_real, pjb, gamma, beta, out);
    // 7) second output = x_imag passthrough
    cudaMemcpyAsync(out + (size_t)ROWS * DD, x_imag,
                    (size_t)ROWS * DD * sizeof(float),
                    cudaMemcpyDeviceToDevice);
}

// round 4
// speedup vs baseline: 1.5674x; 1.5674x over previous
#include <cuda_runtime.h>
#include <math.h>
#include <stdint.h>

// ---------------------------------------------------------------------------
// Problem constants
// ---------------------------------------------------------------------------
#define BB        2
#define LL        2048
#define DD        1024
#define HH        16
#define NPH       128
#define HD        64
#define ROWS      (BB*LL)  // 4096

__device__ __forceinline__ float qa_const() {
    return (float)(0.35355339059327376 * 1.4426950408889634);
}
__device__ __forceinline__ float qb_const() {
    return (float)(8.0 * 0.35355339059327376 * 1.4426950408889634);
}

// ---------------------------------------------------------------------------
// f32x2 packed helpers (attention kernel)
// ---------------------------------------------------------------------------
__device__ __forceinline__ unsigned long long pk2(float lo, float hi) {
    unsigned long long r;
    asm("mov.b64 %0, {%1, %2};" : "=l"(r) : "f"(lo), "f"(hi));
    return r;
}
__device__ __forceinline__ float2 up2(unsigned long long v) {
    float2 r;
    asm("mov.b64 {%0, %1}, %2;" : "=f"(r.x), "=f"(r.y) : "l"(v));
    return r;
}
#define FMA2(d, a, b) asm("fma.rn.f32x2 %0, %1, %2, %0;" : "+l"(d) : "l"(a), "l"(b))

// ---------------------------------------------------------------------------
// mma.sync tf32 helpers (baseline PTX; runs on sm_100 via fallback HMMA)
// ---------------------------------------------------------------------------
__device__ __forceinline__ uint32_t f2tf(float f) {
    uint32_t r;
    asm("cvt.rna.tf32.f32 %0, %1;" : "=r"(r) : "f"(f));
    return r;
}
#define MMA_TF32(cc, a, b)                                                     \
    asm("mma.sync.aligned.m16n8k8.row.col.f32.tf32.tf32.f32 "                  \
        "{%0,%1,%2,%3}, {%4,%5,%6,%7}, {%8,%9}, {%0,%1,%2,%3};"                \
        : "+f"((cc)[0]), "+f"((cc)[1]), "+f"((cc)[2]), "+f"((cc)[3])           \
        : "r"((a)[0]), "r"((a)[1]), "r"((a)[2]), "r"((a)[3]),                  \
          "r"((b)[0]), "r"((b)[1]))

__device__ __forceinline__ uint32_t s2u(const void* p) {
    uint32_t a;
    asm("{ .reg .u64 t; cvta.to.shared.u64 t, %1; cvt.u32.u64 %0, t; }"
        : "=r"(a) : "l"(p));
    return a;
}
__device__ __forceinline__ void cpa16(uint32_t dst, const void* src) {
    asm volatile("cp.async.cg.shared.global [%0], [%1], 16;"
                 :: "r"(dst), "l"(src));
}

// ---------------------------------------------------------------------------
// Scratch (no allocation allowed)
// ---------------------------------------------------------------------------
static __device__ float g_wqk [256 * DD];         // [Wq ; Wk]
static __device__ float g_phqk[ROWS * 256];       // Q phases [0:128), K [128:256)
static __device__ float g_qf  [BB * HH * LL * 16];
static __device__ float g_kf  [BB * HH * LL * 16];
static __device__ float g_v   [ROWS * DD];
static __device__ float g_ao  [ROWS * DD];
static __device__ float g_pj  [ROWS * DD];

// ---------------------------------------------------------------------------
// Tensor-core GEMM: C[M,N] = A[M,K] * B[N,K]^T, fp32 in/out, tf32 mma.sync.
// CTA 128x128, 8 warps (2x4), warp tile 64x32, K-tile 16, cp.async dbl-buffer.
// grid: (N/128, M/128). K % 16 == 0.
// ---------------------------------------------------------------------------
#define SMS 20                      // smem row stride (floats): conflict-free
__global__ __launch_bounds__(256, 2) void gemm_mma(
    const float* __restrict__ A, const float* __restrict__ B,
    float* __restrict__ C, int N, int K)
{
    __shared__ __align__(16) float sm[4 * 128 * SMS];   // As0,As1,Bs0,Bs1

    const int tid  = threadIdx.x;
    const int wid  = tid >> 5, lane = tid & 31;
    const int wm   = wid & 1, wn = wid >> 1;            // 2 x 4 warp grid
    const int g    = lane >> 2, tg = lane & 3;
    const int rowBase = blockIdx.y * 128;
    const int colBase = blockIdx.x * 128;

    const uint32_t smu = s2u(sm);
    const int r1 = tid >> 2,       c1 = tid & 3;        // chunk tid
    const int r2 = (tid + 256) >> 2, c2 = tid & 3;      // chunk tid+256

    float c[4][4][4] = {};

    auto issue = [&](int t) {
        const int buf = t & 1;
        const uint32_t ab = smu + (uint32_t)(buf * 128 * SMS) * 4u;
        const uint32_t bb = smu + (uint32_t)((2 + buf) * 128 * SMS) * 4u;
        const float* Ag = A + (size_t)rowBase * K + t * 16;
        const float* Bg = B + (size_t)colBase * K + t * 16;
        cpa16(ab + (uint32_t)(r1 * SMS + c1 * 4) * 4u, Ag + (size_t)r1 * K + c1 * 4);
        cpa16(ab + (uint32_t)(r2 * SMS + c2 * 4) * 4u, Ag + (size_t)r2 * K + c2 * 4);
        cpa16(bb + (uint32_t)(r1 * SMS + c1 * 4) * 4u, Bg + (size_t)r1 * K + c1 * 4);
        cpa16(bb + (uint32_t)(r2 * SMS + c2 * 4) * 4u, Bg + (size_t)r2 * K + c2 * 4);
        asm volatile("cp.async.commit_group;");
    };

    const int NT = K >> 4;
    issue(0);
#pragma unroll 1
    for (int t = 0; t < NT; t++) {
        if (t + 1 < NT) {
            issue(t + 1);
            asm volatile("cp.async.wait_group 1;");
        } else {
            asm volatile("cp.async.wait_group 0;");
        }
        __syncthreads();
        const float* Ab = sm + (t & 1) * 128 * SMS;
        const float* Bb = sm + (2 + (t & 1)) * 128 * SMS;
#pragma unroll
        for (int kk = 0; kk < 2; kk++) {
            uint32_t af[4][4], bf[4][2];
#pragma unroll
            for (int mt = 0; mt < 4; mt++) {
                const float* p = Ab + (wm * 64 + mt * 16 + g) * SMS + kk * 8 + tg;
                af[mt][0] = f2tf(p[0]);
                af[mt][1] = f2tf(p[8 * SMS]);
                af[mt][2] = f2tf(p[4]);
                af[mt][3] = f2tf(p[8 * SMS + 4]);
            }
#pragma unroll
            for (int nt = 0; nt < 4; nt++) {
                const float* p = Bb + (wn * 32 + nt * 8 + g) * SMS + kk * 8 + tg;
                bf[nt][0] = f2tf(p[0]);
                bf[nt][1] = f2tf(p[4]);
            }
#pragma unroll
            for (int mt = 0; mt < 4; mt++)
#pragma unroll
                for (int nt = 0; nt < 4; nt++)
                    MMA_TF32(c[mt][nt], af[mt], bf[nt]);
        }
        __syncthreads();
    }

#pragma unroll
    for (int mt = 0; mt < 4; mt++) {
        const int row = rowBase + wm * 64 + mt * 16 + g;
#pragma unroll
        for (int nt = 0; nt < 4; nt++) {
            const int col = colBase + wn * 32 + nt * 8 + tg * 2;
            *(float2*)&C[(size_t)row * N + col] =
                make_float2(c[mt][nt][0], c[mt][nt][1]);
            *(float2*)&C[(size_t)(row + 8) * N + col] =
                make_float2(c[mt][nt][2], c[mt][nt][3]);
        }
    }
}

// ---------------------------------------------------------------------------
// Features: phase -> (cos, sin) with bias + positional phase.
// phqk layout: row stride 256, Q at [0:128), K at [128:256).
// ---------------------------------------------------------------------------
__global__ void feat_kernel(const float* __restrict__ phqk,
                            const float* __restrict__ bq,
                            const float* __restrict__ bk,
                            float* __restrict__ qfo, float* __restrict__ kfo)
{
    int idx = blockIdx.x * blockDim.x + threadIdx.x;
    if (idx >= ROWS * NPH) return;
    int p   = idx & (NPH - 1);
    int row = idx >> 7;
    int l   = row & (LL - 1);
    int b   = row >> 11;
    int h   = p >> 3;
    int pp  = p & 7;
    int k2  = p & ~1;

    const float LC = (float)(13.287712379549449 / 128.0);
    float invf = exp2f(-(float)k2 * LC);
    float pos  = (float)l * invf;

    size_t ob = (((size_t)b * HH + h) * LL + l) * 16 + pp;
    const float* pr = phqk + (size_t)row * 256;
    float s, c;
    sincosf(pr[p] + bq[p] + pos, &s, &c);
    qfo[ob] = c; qfo[ob + 8] = s;
    sincosf(pr[128 + p] + bk[p] + pos, &s, &c);
    kfo[ob] = c; kfo[ob + 8] = s;
}

// ---------------------------------------------------------------------------
// Attention, head-dim split: grid (B*H=32, 8, 2). blockIdx.z picks 32 of the
// 64 head dims. Complementary query-tile pair (y, 15-y) -> uniform load.
// Fixed-max softmax (scores bounded by sqrt(8)); single streaming pass.
// ---------------------------------------------------------------------------
__global__ __launch_bounds__(128) void attn_kernel(
    const float* __restrict__ qf, const float* __restrict__ kf,
    const float* __restrict__ V, float* __restrict__ Out)
{
    __shared__ __align__(16) float kfs[64 * 16];
    __shared__ __align__(16) float vs[64 * 32];

    const int bh  = blockIdx.x;
    const int b   = bh >> 4;
    const int h   = bh & 15;
    const int z   = blockIdx.z;
    const int tid = threadIdx.x;
    const float QA = qa_const();
    const float QB = qb_const();

#pragma unroll 1
    for (int part = 0; part < 2; part++) {
        const int qt   = part ? (15 - (int)blockIdx.y) : (int)blockIdx.y;
        const int qrow = qt * 128 + tid;

        const unsigned long long* qp =
            (const unsigned long long*)(qf + ((size_t)bh * LL + qrow) * 16);
        unsigned long long qd[8];
#pragma unroll
        for (int i = 0; i < 8; i++) qd[i] = qp[i];

        unsigned long long o2[16];
#pragma unroll
        for (int i = 0; i < 16; i++) o2[i] = 0ULL;
        float lsum = 0.f;

        const int ntiles = qt * 2 + 2;
        for (int kt = 0; kt < ntiles; kt++) {
            const int c0 = kt * 64;
            __syncthreads();
            { // K-feature tile: 64 x 16
                const float4* src =
                    (const float4*)(kf + ((size_t)bh * LL + c0) * 16);
                float4* dst = (float4*)kfs;
                dst[tid]       = src[tid];
                dst[tid + 128] = src[tid + 128];
            }
            { // V tile: 64 rows x 32 dims (this block's half)
                const float* vb = V + ((size_t)b * LL + c0) * DD + h * HD + z * 32;
                float4* dst = (float4*)vs;
#pragma unroll
                for (int r = 0; r < 4; r++) {
                    int f  = tid + r * 128;
                    int j  = f >> 3;
                    int d4 = f & 7;
                    dst[f] = *(const float4*)(vb + (size_t)j * DD + (d4 << 2));
                }
            }
            __syncthreads();

            const int jmax = min(63, qrow - c0);
            for (int j = 0; j <= jmax; j++) {
                const unsigned long long* kp =
                    (const unsigned long long*)(kfs + (j << 4));
                unsigned long long acc = 0ULL;
#pragma unroll
                for (int c = 0; c < 8; c++) FMA2(acc, qd[c], kp[c]);
                float2 av = up2(acc);
                float s = av.x + av.y;
                float p = exp2f(fmaf(s, QA, -QB));
                lsum += p;
                unsigned long long p2 = pk2(p, p);
                const unsigned long long* vr =
                    (const unsigned long long*)(vs + (j << 5));
#pragma unroll
                for (int d = 0; d < 16; d++) FMA2(o2[d], p2, vr[d]);
            }
        }

        const float inv = 1.0f / lsum;
        float* op = Out + ((size_t)b * LL + qrow) * DD + (h << 6) + z * 32;
#pragma unroll
        for (int d4 = 0; d4 < 8; d4++) {
            float2 x0 = up2(o2[2 * d4]);
            float2 x1 = up2(o2[2 * d4 + 1]);
            *(float4*)(op + (d4 << 2)) =
                make_float4(x0.x * inv, x0.y * inv, x1.x * inv, x1.y * inv);
        }
    }
}

// ---------------------------------------------------------------------------
// Residual + LayerNorm
// ---------------------------------------------------------------------------
__global__ __launch_bounds__(256) void ln_kernel(
    const float* __restrict__ xr, const float* __restrict__ pj,
    const float* __restrict__ gamma, const float* __restrict__ beta,
    float* __restrict__ out)
{
    __shared__ float rs[8], rss[8];
    const int row = blockIdx.x;
    const int t   = threadIdx.x;

    const float4* xv = (const float4*)(xr + (size_t)row * DD);
    const float4* pv = (const float4*)(pj + (size_t)row * DD);
    float4 a = xv[t], c = pv[t];
    float h0 = a.x + c.x, h1 = a.y + c.y, h2 = a.z + c.z, h3 = a.w + c.w;
    float s  = h0 + h1 + h2 + h3;
    float ss = h0 * h0 + h1 * h1 + h2 * h2 + h3 * h3;
#pragma unroll
    for (int o = 16; o > 0; o >>= 1) {
        s  += __shfl_down_sync(0xffffffffu, s,  o);
        ss += __shfl_down_sync(0xffffffffu, ss, o);
    }
    if ((t & 31) == 0) { rs[t >> 5] = s; rss[t >> 5] = ss; }
    __syncthreads();
    float st = 0.f, sst = 0.f;
#pragma unroll
    for (int w = 0; w < 8; w++) { st += rs[w]; sst += rss[w]; }
    const float mu  = st * (1.0f / DD);
    const float var = sst * (1.0f / DD) - mu * mu;
    const float inv = rsqrtf(var + 1e-5f);

    float4 g  = ((const float4*)gamma)[t];
    float4 be = ((const float4*)beta)[t];
    float4 o4 = make_float4((h0 - mu) * inv * g.x + be.x,
                            (h1 - mu) * inv * g.y + be.y,
                            (h2 - mu) * inv * g.z + be.z,
                            (h3 - mu) * inv * g.w + be.w);
    ((float4*)(out + (size_t)row * DD))[t] = o4;
}

// ---------------------------------------------------------------------------
// Launch
// ---------------------------------------------------------------------------
extern "C" void kernel_launch(void* const* d_in, const int* in_sizes, int n_in,
                              void* d_out, int out_size)
{
    const float* x_real = (const float*)d_in[0];
    const float* x_imag = (const float*)d_in[1];
    const float* Wq     = (const float*)d_in[2];
    const float* bq     = (const float*)d_in[3];
    const float* Wk     = (const float*)d_in[4];
    const float* bk     = (const float*)d_in[5];
    const float* Wv     = (const float*)d_in[6];
    const float* Wo     = (const float*)d_in[7];
    const float* gamma  = (const float*)d_in[8];
    const float* beta   = (const float*)d_in[9];
    float* out = (float*)d_out;

    float *wqk, *phqk, *qfb, *kfb, *vb, *aob, *pjb;
    cudaGetSymbolAddress((void**)&wqk,  g_wqk);
    cudaGetSymbolAddress((void**)&phqk, g_phqk);
    cudaGetSymbolAddress((void**)&qfb,  g_qf);
    cudaGetSymbolAddress((void**)&kfb,  g_kf);
    cudaGetSymbolAddress((void**)&vb,   g_v);
    cudaGetSymbolAddress((void**)&aob,  g_ao);
    cudaGetSymbolAddress((void**)&pjb,  g_pj);

    // 0) concat Wq || Wk for a single N=256 projection GEMM
    cudaMemcpyAsync(wqk, Wq, (size_t)NPH * DD * sizeof(float),
                    cudaMemcpyDeviceToDevice);
    cudaMemcpyAsync(wqk + (size_t)NPH * DD, Wk, (size_t)NPH * DD * sizeof(float),
                    cudaMemcpyDeviceToDevice);

    // 1) Q/K phase projections (tensor-core tf32)
    gemm_mma<<<dim3(2, 32), 256>>>(x_imag, wqk, phqk, 256, DD);
    // 2) cos/sin features
    feat_kernel<<<(ROWS * NPH) / 256, 256>>>(phqk, bq, bk, qfb, kfb);
    // 3) V projection
    gemm_mma<<<dim3(8, 32), 256>>>(x_real, Wv, vb, DD, DD);
    // 4) causal interference attention (head-dim split)
    attn_kernel<<<dim3(BB * HH, 8, 2), 128>>>(qfb, kfb, vb, aob);
    // 5) output projection
    gemm_mma<<<dim3(8, 32), 256>>>(aob, Wo, pjb, DD, DD);
    // 6) residual + LayerNorm
    ln_kernel<<<ROWS, 256>>>(x_real, pjb, gamma, beta, out);
    // 7) second output = x_imag passthrough
    cudaMemcpyAsync(out + (size_t)ROWS * DD, x_imag,
                    (size_t)ROWS * DD * sizeof(float),
                    cudaMemcpyDeviceToDevice);
}

// round 6
// speedup vs baseline: 3.5043x; 2.2357x over previous
#include <cuda_runtime.h>
#include <math.h>
#include <stdint.h>

// ---------------------------------------------------------------------------
// Problem constants
// ---------------------------------------------------------------------------
#define BB        2
#define LL        2048
#define DD        1024
#define HH        16
#define NPH       128
#define HD        64
#define ROWS      (BB*LL)  // 4096

__device__ __forceinline__ float qa_const() {
    return (float)(0.35355339059327376 * 1.4426950408889634);
}
__device__ __forceinline__ float qb_const() {
    return (float)(8.0 * 0.35355339059327376 * 1.4426950408889634);
}

// ---------------------------------------------------------------------------
// PTX helpers
// ---------------------------------------------------------------------------
__device__ __forceinline__ uint32_t f2tf(float f) {
    uint32_t r;
    asm("cvt.rna.tf32.f32 %0, %1;" : "=r"(r) : "f"(f));
    return r;
}
// pack {lo, hi} floats -> bf16x2 (lo in low 16 bits)
__device__ __forceinline__ uint32_t pkbf(float lo, float hi) {
    uint32_t r;
    asm("cvt.rn.bf16x2.f32 %0, %1, %2;" : "=r"(r) : "f"(hi), "f"(lo));
    return r;
}
__device__ __forceinline__ uint32_t s2u(const void* p) {
    uint32_t a;
    asm("{ .reg .u64 t; cvta.to.shared.u64 t, %1; cvt.u32.u64 %0, t; }"
        : "=r"(a) : "l"(p));
    return a;
}
__device__ __forceinline__ void cpa16(uint32_t dst, const void* src) {
    asm volatile("cp.async.cg.shared.global [%0], [%1], 16;"
                 :: "r"(dst), "l"(src));
}

#define MMA_TF32(cc, a, b0, b1)                                                \
    asm("mma.sync.aligned.m16n8k8.row.col.f32.tf32.tf32.f32 "                  \
        "{%0,%1,%2,%3}, {%4,%5,%6,%7}, {%8,%9}, {%0,%1,%2,%3};"                \
        : "+f"((cc)[0]), "+f"((cc)[1]), "+f"((cc)[2]), "+f"((cc)[3])           \
        : "r"((a)[0]), "r"((a)[1]), "r"((a)[2]), "r"((a)[3]),                  \
          "r"(b0), "r"(b1))

#define MMA_BF16(cc, a, b0, b1)                                                \
    asm("mma.sync.aligned.m16n8k16.row.col.f32.bf16.bf16.f32 "                 \
        "{%0,%1,%2,%3}, {%4,%5,%6,%7}, {%8,%9}, {%0,%1,%2,%3};"                \
        : "+f"((cc)[0]), "+f"((cc)[1]), "+f"((cc)[2]), "+f"((cc)[3])           \
        : "r"((a)[0]), "r"((a)[1]), "r"((a)[2]), "r"((a)[3]),                  \
          "r"(b0), "r"(b1))

#define LDSM_T4(r0, r1, r2, r3, addr)                                          \
    asm volatile("ldmatrix.sync.aligned.m8n8.x4.trans.shared.b16 "             \
                 "{%0,%1,%2,%3}, [%4];"                                        \
                 : "=r"(r0), "=r"(r1), "=r"(r2), "=r"(r3) : "r"(addr))

// ---------------------------------------------------------------------------
// Scratch (no allocation allowed)
// ---------------------------------------------------------------------------
static __device__ float          g_wqk [256 * DD];   // [Wq ; Wk]
static __device__ float          g_phqk[ROWS * 256]; // Q [0:128), K [128:256)
static __device__ float          g_qf  [BB * HH * LL * 16];
static __device__ float          g_kf  [BB * HH * LL * 16];
static __device__ unsigned short g_vbf [ROWS * DD];  // V in bf16
static __device__ float          g_ao  [ROWS * DD];
static __device__ float          g_pj  [ROWS * DD];

// ---------------------------------------------------------------------------
// Tensor-core GEMM: C[M,N] = A[M,K] * B[N,K]^T, tf32 mma.sync.
// If Cb != nullptr, write bf16 output instead of fp32.
// ---------------------------------------------------------------------------
#define SMS 20
__global__ __launch_bounds__(256, 2) void gemm_mma(
    const float* __restrict__ A, const float* __restrict__ B,
    float* __restrict__ C, unsigned short* __restrict__ Cb, int N, int K)
{
    __shared__ __align__(16) float sm[4 * 128 * SMS];

    const int tid  = threadIdx.x;
    const int wid  = tid >> 5, lane = tid & 31;
    const int wm   = wid & 1, wn = wid >> 1;
    const int g    = lane >> 2, tg = lane & 3;
    const int rowBase = blockIdx.y * 128;
    const int colBase = blockIdx.x * 128;

    const uint32_t smu = s2u(sm);
    const int r1 = tid >> 2,         c1 = tid & 3;
    const int r2 = (tid + 256) >> 2, c2 = tid & 3;

    float c[4][4][4] = {};

    auto issue = [&](int t) {
        const int buf = t & 1;
        const uint32_t ab = smu + (uint32_t)(buf * 128 * SMS) * 4u;
        const uint32_t bb = smu + (uint32_t)((2 + buf) * 128 * SMS) * 4u;
        const float* Ag = A + (size_t)rowBase * K + t * 16;
        const float* Bg = B + (size_t)colBase * K + t * 16;
        cpa16(ab + (uint32_t)(r1 * SMS + c1 * 4) * 4u, Ag + (size_t)r1 * K + c1 * 4);
        cpa16(ab + (uint32_t)(r2 * SMS + c2 * 4) * 4u, Ag + (size_t)r2 * K + c2 * 4);
        cpa16(bb + (uint32_t)(r1 * SMS + c1 * 4) * 4u, Bg + (size_t)r1 * K + c1 * 4);
        cpa16(bb + (uint32_t)(r2 * SMS + c2 * 4) * 4u, Bg + (size_t)r2 * K + c2 * 4);
        asm volatile("cp.async.commit_group;");
    };

    const int NT = K >> 4;
    issue(0);
#pragma unroll 1
    for (int t = 0; t < NT; t++) {
        if (t + 1 < NT) {
            issue(t + 1);
            asm volatile("cp.async.wait_group 1;");
        } else {
            asm volatile("cp.async.wait_group 0;");
        }
        __syncthreads();
        const float* Ab = sm + (t & 1) * 128 * SMS;
        const float* Bb = sm + (2 + (t & 1)) * 128 * SMS;
#pragma unroll
        for (int kk = 0; kk < 2; kk++) {
            uint32_t af[4][4], bf[4][2];
#pragma unroll
            for (int mt = 0; mt < 4; mt++) {
                const float* p = Ab + (wm * 64 + mt * 16 + g) * SMS + kk * 8 + tg;
                af[mt][0] = f2tf(p[0]);
                af[mt][1] = f2tf(p[8 * SMS]);
                af[mt][2] = f2tf(p[4]);
                af[mt][3] = f2tf(p[8 * SMS + 4]);
            }
#pragma unroll
            for (int nt = 0; nt < 4; nt++) {
                const float* p = Bb + (wn * 32 + nt * 8 + g) * SMS + kk * 8 + tg;
                bf[nt][0] = f2tf(p[0]);
                bf[nt][1] = f2tf(p[4]);
            }
#pragma unroll
            for (int mt = 0; mt < 4; mt++)
#pragma unroll
                for (int nt = 0; nt < 4; nt++)
                    MMA_TF32(c[mt][nt], af[mt], bf[nt][0], bf[nt][1]);
        }
        __syncthreads();
    }

#pragma unroll
    for (int mt = 0; mt < 4; mt++) {
        const int row = rowBase + wm * 64 + mt * 16 + g;
#pragma unroll
        for (int nt = 0; nt < 4; nt++) {
            const int col = colBase + wn * 32 + nt * 8 + tg * 2;
            if (Cb) {
                *(uint32_t*)&Cb[(size_t)row * N + col] =
                    pkbf(c[mt][nt][0], c[mt][nt][1]);
                *(uint32_t*)&Cb[(size_t)(row + 8) * N + col] =
                    pkbf(c[mt][nt][2], c[mt][nt][3]);
            } else {
                *(float2*)&C[(size_t)row * N + col] =
                    make_float2(c[mt][nt][0], c[mt][nt][1]);
                *(float2*)&C[(size_t)(row + 8) * N + col] =
                    make_float2(c[mt][nt][2], c[mt][nt][3]);
            }
        }
    }
}

// ---------------------------------------------------------------------------
// Features: phase -> (cos, sin) with bias + positional phase.
// ---------------------------------------------------------------------------
__global__ void feat_kernel(const float* __restrict__ phqk,
                            const float* __restrict__ bq,
                            const float* __restrict__ bk,
                            float* __restrict__ qfo, float* __restrict__ kfo)
{
    int idx = blockIdx.x * blockDim.x + threadIdx.x;
    if (idx >= ROWS * NPH) return;
    int p   = idx & (NPH - 1);
    int row = idx >> 7;
    int l   = row & (LL - 1);
    int b   = row >> 11;
    int h   = p >> 3;
    int pp  = p & 7;
    int k2  = p & ~1;

    const float LC = (float)(13.287712379549449 / 128.0);
    float invf = exp2f(-(float)k2 * LC);
    float pos  = (float)l * invf;

    size_t ob = (((size_t)b * HH + h) * LL + l) * 16 + pp;
    const float* pr = phqk + (size_t)row * 256;
    float s, c;
    sincosf(pr[p] + bq[p] + pos, &s, &c);
    qfo[ob] = c; qfo[ob + 8] = s;
    sincosf(pr[128 + p] + bk[p] + pos, &s, &c);
    kfo[ob] = c; kfo[ob + 8] = s;
}

// ---------------------------------------------------------------------------
// Tensor-core flash attention. grid (B*H=32, 8), 128 threads (4 warps).
// Each block: query-tile pair (y, 15-y), 128 q rows per tile (32 per warp).
// Key tiles of 64. S: tf32 mma (k=16). P: bf16 (FA2 C->A frag reuse).
// PV: bf16 mma with ldmatrix.trans V fragments. Fixed-max softmax.
// ---------------------------------------------------------------------------
#define VSTR 72   // V smem row stride in bf16 (conflict-free ldmatrix phases)
__global__ __launch_bounds__(128) void attn_tc(
    const float* __restrict__ qf, const float* __restrict__ kf,
    const unsigned short* __restrict__ Vb, float* __restrict__ Out)
{
    __shared__ __align__(16) float          Ks[2][64 * SMS];
    __shared__ __align__(16) unsigned short Vs[2][64 * VSTR];

    const int bh   = blockIdx.x;
    const int b    = bh >> 4;
    const int h    = bh & 15;
    const int tid  = threadIdx.x;
    const int warp = tid >> 5;
    const int lane = tid & 31;
    const int g    = lane >> 2, tg = lane & 3;
    const float QA = qa_const();
    const float QB = qb_const();

    const float* qfb = qf + (size_t)bh * LL * 16;
    const float* kfb = kf + (size_t)bh * LL * 16;
    const unsigned short* vgb = Vb + (size_t)b * LL * DD + h * HD;

    const uint32_t Ksu = s2u(Ks);
    const uint32_t Vsu = s2u(Vs);
    // ldmatrix per-thread address offset within a V buffer
    const uint32_t lm_off = (uint32_t)((lane & 15) * VSTR + (lane >> 4) * 8) * 2u;

    auto fill = [&](int kt, int buf) {
        const int c0 = kt * 64;
        const uint32_t kb = Ksu + (uint32_t)buf * (64 * SMS * 4);
#pragma unroll
        for (int u = 0; u < 2; u++) {
            int idx = tid * 2 + u;
            int r = idx >> 2, c4 = idx & 3;
            cpa16(kb + (uint32_t)(r * SMS + c4 * 4) * 4u,
                  kfb + (size_t)(c0 + r) * 16 + c4 * 4);
        }
        const uint32_t vb = Vsu + (uint32_t)buf * (64 * VSTR * 2);
#pragma unroll
        for (int u = 0; u < 4; u++) {
            int idx = tid * 4 + u;
            int r = idx >> 3, c8 = idx & 7;
            cpa16(vb + (uint32_t)(r * VSTR + c8 * 8) * 2u,
                  vgb + (size_t)(c0 + r) * DD + c8 * 8);
        }
        asm volatile("cp.async.commit_group;");
    };

#pragma unroll 1
    for (int part = 0; part < 2; part++) {
        const int qt = part ? (15 - (int)blockIdx.y) : (int)blockIdx.y;
        const int q0 = qt * 128;
        const int ntiles = 2 * qt + 2;
        const int wrow = q0 + warp * 32;          // warp's first q row

        // Q fragments (tf32), rows wrow + mt*16 + {g, g+8}
        uint32_t aq[2][2][4];
#pragma unroll
        for (int mt = 0; mt < 2; mt++) {
            const float* qp = qfb + (size_t)(wrow + mt * 16) * 16;
#pragma unroll
            for (int kk = 0; kk < 2; kk++) {
                aq[mt][kk][0] = f2tf(qp[(size_t)g * 16 + kk * 8 + tg]);
                aq[mt][kk][1] = f2tf(qp[(size_t)(g + 8) * 16 + kk * 8 + tg]);
                aq[mt][kk][2] = f2tf(qp[(size_t)g * 16 + kk * 8 + tg + 4]);
                aq[mt][kk][3] = f2tf(qp[(size_t)(g + 8) * 16 + kk * 8 + tg + 4]);
            }
        }

        float o[2][8][4] = {};
        float ls[2][2]   = {};

        fill(0, 0);
#pragma unroll 1
        for (int kt = 0; kt < ntiles; kt++) {
            const int buf = kt & 1;
            if (kt + 1 < ntiles) {
                fill(kt + 1, buf ^ 1);
                asm volatile("cp.async.wait_group 1;");
            } else {
                asm volatile("cp.async.wait_group 0;");
            }
            __syncthreads();

            const int c0 = kt * 64;
            if (c0 <= wrow + 31) {                      // not fully masked
                const bool domask = (c0 + 63 > wrow);
                const float* Kb = Ks[buf];
                const uint32_t vbase = Vsu + (uint32_t)buf * (64 * VSTR * 2) + lm_off;

#pragma unroll
                for (int mt = 0; mt < 2; mt++) {
                    // ---- S = Qf Kf^T (tf32) ----
                    float s[8][4] = {};
#pragma unroll
                    for (int nd = 0; nd < 8; nd++) {
                        const float* kr = Kb + (nd * 8 + g) * SMS;
                        uint32_t b0 = f2tf(kr[tg]);
                        uint32_t b1 = f2tf(kr[tg + 4]);
                        MMA_TF32(s[nd], aq[mt][0], b0, b1);
                        b0 = f2tf(kr[8 + tg]);
                        b1 = f2tf(kr[12 + tg]);
                        MMA_TF32(s[nd], aq[mt][1], b0, b1);
                    }
                    // ---- softmax (fixed max) + pack P to bf16 A-frags ----
                    const int row0 = wrow + mt * 16 + g;
                    uint32_t pk[16];
#pragma unroll
                    for (int nd = 0; nd < 8; nd++) {
                        const int col = c0 + nd * 8 + 2 * tg;
                        float p0 = exp2f(fmaf(s[nd][0], QA, -QB));
                        float p1 = exp2f(fmaf(s[nd][1], QA, -QB));
                        float p2 = exp2f(fmaf(s[nd][2], QA, -QB));
                        float p3 = exp2f(fmaf(s[nd][3], QA, -QB));
                        if (domask) {
                            if (col > row0)         p0 = 0.f;
                            if (col + 1 > row0)     p1 = 0.f;
                            if (col > row0 + 8)     p2 = 0.f;
                            if (col + 1 > row0 + 8) p3 = 0.f;
                        }
                        ls[mt][0] += p0 + p1;
                        ls[mt][1] += p2 + p3;
                        pk[2 * nd]     = pkbf(p0, p1);
                        pk[2 * nd + 1] = pkbf(p2, p3);
                    }
                    // ---- O += P V (bf16) ----
#pragma unroll
                    for (int kv = 0; kv < 4; kv++) {
                        const uint32_t* a = &pk[4 * kv];
#pragma unroll
                        for (int np = 0; np < 4; np++) {
                            uint32_t r0, r1, r2, r3;
                            LDSM_T4(r0, r1, r2, r3,
                                    vbase + (uint32_t)(kv * 16 * VSTR + np * 16) * 2u);
                            MMA_BF16(o[mt][2 * np],     a, r0, r1);
                            MMA_BF16(o[mt][2 * np + 1], a, r2, r3);
                        }
                    }
                }
            }
            __syncthreads();
        }

        // quad-reduce row sums (lanes in a quad share g -> same rows)
#pragma unroll
        for (int mt = 0; mt < 2; mt++)
#pragma unroll
            for (int r = 0; r < 2; r++) {
                float v = ls[mt][r];
                v += __shfl_xor_sync(0xffffffffu, v, 1);
                v += __shfl_xor_sync(0xffffffffu, v, 2);
                ls[mt][r] = 1.0f / v;
            }

#pragma unroll
        for (int mt = 0; mt < 2; mt++) {
            const int row = wrow + mt * 16 + g;
            const float i0 = ls[mt][0], i1 = ls[mt][1];
#pragma unroll
            for (int nd = 0; nd < 8; nd++) {
                const int col = h * HD + nd * 8 + 2 * tg;
                *(float2*)&Out[(size_t)(b * LL + row) * DD + col] =
                    make_float2(o[mt][nd][0] * i0, o[mt][nd][1] * i0);
                *(float2*)&Out[(size_t)(b * LL + row + 8) * DD + col] =
                    make_float2(o[mt][nd][2] * i1, o[mt][nd][3] * i1);
            }
        }
    }
}

// ---------------------------------------------------------------------------
// Residual + LayerNorm
// ---------------------------------------------------------------------------
__global__ __launch_bounds__(256) void ln_kernel(
    const float* __restrict__ xr, const float* __restrict__ pj,
    const float* __restrict__ gamma, const float* __restrict__ beta,
    float* __restrict__ out)
{
    __shared__ float rs[8], rss[8];
    const int row = blockIdx.x;
    const int t   = threadIdx.x;

    const float4* xv = (const float4*)(xr + (size_t)row * DD);
    const float4* pv = (const float4*)(pj + (size_t)row * DD);
    float4 a = xv[t], c = pv[t];
    float h0 = a.x + c.x, h1 = a.y + c.y, h2 = a.z + c.z, h3 = a.w + c.w;
    float s  = h0 + h1 + h2 + h3;
    float ss = h0 * h0 + h1 * h1 + h2 * h2 + h3 * h3;
#pragma unroll
    for (int o = 16; o > 0; o >>= 1) {
        s  += __shfl_down_sync(0xffffffffu, s,  o);
        ss += __shfl_down_sync(0xffffffffu, ss, o);
    }
    if ((t & 31) == 0) { rs[t >> 5] = s; rss[t >> 5] = ss; }
    __syncthreads();
    float st = 0.f, sst = 0.f;
#pragma unroll
    for (int w = 0; w < 8; w++) { st += rs[w]; sst += rss[w]; }
    const float mu  = st * (1.0f / DD);
    const float var = sst * (1.0f / DD) - mu * mu;
    const float inv = rsqrtf(var + 1e-5f);

    float4 g  = ((const float4*)gamma)[t];
    float4 be = ((const float4*)beta)[t];
    float4 o4 = make_float4((h0 - mu) * inv * g.x + be.x,
                            (h1 - mu) * inv * g.y + be.y,
                            (h2 - mu) * inv * g.z + be.z,
                            (h3 - mu) * inv * g.w + be.w);
    ((float4*)(out + (size_t)row * DD))[t] = o4;
}

// ---------------------------------------------------------------------------
// Launch
// ---------------------------------------------------------------------------
extern "C" void kernel_launch(void* const* d_in, const int* in_sizes, int n_in,
                              void* d_out, int out_size)
{
    const float* x_real = (const float*)d_in[0];
    const float* x_imag = (const float*)d_in[1];
    const float* Wq     = (const float*)d_in[2];
    const float* bq     = (const float*)d_in[3];
    const float* Wk     = (const float*)d_in[4];
    const float* bk     = (const float*)d_in[5];
    const float* Wv     = (const float*)d_in[6];
    const float* Wo     = (const float*)d_in[7];
    const float* gamma  = (const float*)d_in[8];
    const float* beta   = (const float*)d_in[9];
    float* out = (float*)d_out;

    float *wqk, *phqk, *qfb, *kfb, *aob, *pjb;
    unsigned short* vbf;
    cudaGetSymbolAddress((void**)&wqk,  g_wqk);
    cudaGetSymbolAddress((void**)&phqk, g_phqk);
    cudaGetSymbolAddress((void**)&qfb,  g_qf);
    cudaGetSymbolAddress((void**)&kfb,  g_kf);
    cudaGetSymbolAddress((void**)&vbf,  g_vbf);
    cudaGetSymbolAddress((void**)&aob,  g_ao);
    cudaGetSymbolAddress((void**)&pjb,  g_pj);

    // 0) concat Wq || Wk for a single N=256 projection GEMM
    cudaMemcpyAsync(wqk, Wq, (size_t)NPH * DD * sizeof(float),
                    cudaMemcpyDeviceToDevice);
    cudaMemcpyAsync(wqk + (size_t)NPH * DD, Wk, (size_t)NPH * DD * sizeof(float),
                    cudaMemcpyDeviceToDevice);

    // 1) Q/K phase projections (tf32 tensor cores)
    gemm_mma<<<dim3(2, 32), 256>>>(x_imag, wqk, phqk, nullptr, 256, DD);
    // 2) cos/sin features
    feat_kernel<<<(ROWS * NPH) / 256, 256>>>(phqk, bq, bk, qfb, kfb);
    // 3) V projection -> bf16 output
    gemm_mma<<<dim3(8, 32), 256>>>(x_real, Wv, nullptr, vbf, DD, DD);
    // 4) tensor-core flash attention
    attn_tc<<<dim3(BB * HH, 8), 128>>>(qfb, kfb, vbf, aob);
    // 5) output projection
    gemm_mma<<<dim3(8, 32), 256>>>(aob, Wo, pjb, nullptr, DD, DD);
    // 6) residual + LayerNorm
    ln_kernel<<<ROWS, 256>>>(x_real, pjb, gamma, beta, out);
    // 7) second output = x_imag passthrough
    cudaMemcpyAsync(out + (size_t)ROWS * DD, x_imag,
                    (size_t)ROWS * DD * sizeof(float),
                    cudaMemcpyDeviceToDevice);
}

// round 9
// speedup vs baseline: 3.7017x; 1.0563x over previous
#include <cuda_runtime.h>
#include <math.h>
#include <stdint.h>

// ---------------------------------------------------------------------------
// Problem constants
// ---------------------------------------------------------------------------
#define BB        2
#define LL        2048
#define DD        1024
#define HH        16
#define NPH       128
#define HD        64
#define ROWS      (BB*LL)  // 4096

__device__ __forceinline__ float qa_const() {
    return (float)(0.35355339059327376 * 1.4426950408889634);
}
__device__ __forceinline__ float qb_const() {
    return (float)(8.0 * 0.35355339059327376 * 1.4426950408889634);
}

// ---------------------------------------------------------------------------
// PTX helpers
// ---------------------------------------------------------------------------
__device__ __forceinline__ uint32_t f2tf(float f) {
    uint32_t r;
    asm("cvt.rna.tf32.f32 %0, %1;" : "=r"(r) : "f"(f));
    return r;
}
__device__ __forceinline__ uint32_t pkbf(float lo, float hi) {
    uint32_t r;
    asm("cvt.rn.bf16x2.f32 %0, %1, %2;" : "=r"(r) : "f"(hi), "f"(lo));
    return r;
}
__device__ __forceinline__ unsigned short f2h(float f) {
    unsigned short r;
    asm("cvt.rn.f16.f32 %0, %1;" : "=h"(r) : "f"(f));
    return r;
}
__device__ __forceinline__ uint32_t s2u(const void* p) {
    uint32_t a;
    asm("{ .reg .u64 t; cvta.to.shared.u64 t, %1; cvt.u32.u64 %0, t; }"
        : "=r"(a) : "l"(p));
    return a;
}
__device__ __forceinline__ void cpa16(uint32_t dst, const void* src) {
    asm volatile("cp.async.cg.shared.global [%0], [%1], 16;"
                 :: "r"(dst), "l"(src));
}

#define MMA_TF32(cc, a, b0, b1)                                                \
    asm("mma.sync.aligned.m16n8k8.row.col.f32.tf32.tf32.f32 "                  \
        "{%0,%1,%2,%3}, {%4,%5,%6,%7}, {%8,%9}, {%0,%1,%2,%3};"                \
        : "+f"((cc)[0]), "+f"((cc)[1]), "+f"((cc)[2]), "+f"((cc)[3])           \
        : "r"((a)[0]), "r"((a)[1]), "r"((a)[2]), "r"((a)[3]),                  \
          "r"(b0), "r"(b1))

#define MMA_BF16(cc, a, b0, b1)                                                \
    asm("mma.sync.aligned.m16n8k16.row.col.f32.bf16.bf16.f32 "                 \
        "{%0,%1,%2,%3}, {%4,%5,%6,%7}, {%8,%9}, {%0,%1,%2,%3};"                \
        : "+f"((cc)[0]), "+f"((cc)[1]), "+f"((cc)[2]), "+f"((cc)[3])           \
        : "r"((a)[0]), "r"((a)[1]), "r"((a)[2]), "r"((a)[3]),                  \
          "r"(b0), "r"(b1))

#define MMA_F16(cc, a, b0, b1)                                                 \
    asm("mma.sync.aligned.m16n8k16.row.col.f32.f16.f16.f32 "                   \
        "{%0,%1,%2,%3}, {%4,%5,%6,%7}, {%8,%9}, {%0,%1,%2,%3};"                \
        : "+f"((cc)[0]), "+f"((cc)[1]), "+f"((cc)[2]), "+f"((cc)[3])           \
        : "r"((a)[0]), "r"((a)[1]), "r"((a)[2]), "r"((a)[3]),                  \
          "r"(b0), "r"(b1))

#define LDSM_T4(r0, r1, r2, r3, addr)                                          \
    asm volatile("ldmatrix.sync.aligned.m8n8.x4.trans.shared.b16 "             \
                 "{%0,%1,%2,%3}, [%4];"                                        \
                 : "=r"(r0), "=r"(r1), "=r"(r2), "=r"(r3) : "r"(addr))

#define LDSM_X2(r0, r1, addr)                                                  \
    asm volatile("ldmatrix.sync.aligned.m8n8.x2.shared.b16 "                   \
                 "{%0,%1}, [%2];"                                              \
                 : "=r"(r0), "=r"(r1) : "r"(addr))

// fast sincos: 2-term Cody-Waite reduction + MUFU sin/cos (|x| < ~4000)
__device__ __forceinline__ void fastsc(float x, float* s, float* c) {
    const float INV2PI = 0.15915494309189535f;
    const float P2HI   = 6.2831854820251465f;      // float(2*pi)
    const float P2LO   = -1.7484555314695172e-07f; // 2*pi - P2HI
    float n = rintf(x * INV2PI);
    float r = fmaf(n, -P2HI, x);
    r = fmaf(n, -P2LO, r);
    *s = __sinf(r);
    *c = __cosf(r);
}

// ---------------------------------------------------------------------------
// Scratch
// ---------------------------------------------------------------------------
static __device__ float          g_wqk [256 * DD];   // [Wq ; Wk]
static __device__ float          g_phqk[ROWS * 256];
static __device__ unsigned short g_qf  [BB * HH * LL * 16];  // fp16 features
static __device__ unsigned short g_kf  [BB * HH * LL * 16];  // fp16 features
static __device__ unsigned short g_vbf [ROWS * DD];          // V in bf16
static __device__ float          g_ao  [ROWS * DD];
static __device__ float          g_pj  [ROWS * DD];

// ---------------------------------------------------------------------------
// Tensor-core GEMM: C[M,N] = A[M,K] * B[N,K]^T, tf32 mma.sync.
// 4-stage cp.async ring, single __syncthreads per K-tile.
// If Cb != nullptr, write bf16 output instead of fp32.
// ---------------------------------------------------------------------------
#define SMS   20
#define GNSTG 4
#define GEMM_SMEM (GNSTG * 2 * 128 * SMS * 4)   // 81920 B

__global__ __launch_bounds__(256, 2) void gemm_mma(
    const float* __restrict__ A, const float* __restrict__ B,
    float* __restrict__ C, unsigned short* __restrict__ Cb, int N, int K)
{
    extern __shared__ __align__(16) float sm[];

    const int tid  = threadIdx.x;
    const int wid  = tid >> 5, lane = tid & 31;
    const int wm   = wid & 1, wn = wid >> 1;
    const int g    = lane >> 2, tg = lane & 3;
    const int rowBase = blockIdx.y * 128;
    const int colBase = blockIdx.x * 128;

    const uint32_t smu = s2u(sm);
    const int r1 = tid >> 2,         c1 = tid & 3;
    const int r2 = (tid + 256) >> 2, c2 = tid & 3;

    float c[4][4][4] = {};

    auto issue = [&](int t) {
        const int buf = t & (GNSTG - 1);
        const uint32_t ab = smu + (uint32_t)(buf * 2 * 128 * SMS) * 4u;
        const uint32_t bb = ab + (uint32_t)(128 * SMS) * 4u;
        const float* Ag = A + (size_t)rowBase * K + t * 16;
        const float* Bg = B + (size_t)colBase * K + t * 16;
        cpa16(ab + (uint32_t)(r1 * SMS + c1 * 4) * 4u, Ag + (size_t)r1 * K + c1 * 4);
        cpa16(ab + (uint32_t)(r2 * SMS + c2 * 4) * 4u, Ag + (size_t)r2 * K + c2 * 4);
        cpa16(bb + (uint32_t)(r1 * SMS + c1 * 4) * 4u, Bg + (size_t)r1 * K + c1 * 4);
        cpa16(bb + (uint32_t)(r2 * SMS + c2 * 4) * 4u, Bg + (size_t)r2 * K + c2 * 4);
        asm volatile("cp.async.commit_group;");
    };

    const int NT = K >> 4;
    issue(0);
    issue(1);
#pragma unroll 1
    for (int t = 0; t < NT; t++) {
        if (t + 2 < NT) {
            issue(t + 2);
            asm volatile("cp.async.wait_group 2;");
        } else if (t + 1 < NT) {
            asm volatile("cp.async.wait_group 1;");
        } else {
            asm volatile("cp.async.wait_group 0;");
        }
        __syncthreads();
        const float* Ab = sm + (t & (GNSTG - 1)) * 2 * 128 * SMS;
        const float* Bb = Ab + 128 * SMS;
#pragma unroll
        for (int kk = 0; kk < 2; kk++) {
            uint32_t af[4][4], bf[4][2];
#pragma unroll
            for (int mt = 0; mt < 4; mt++) {
                const float* p = Ab + (wm * 64 + mt * 16 + g) * SMS + kk * 8 + tg;
                af[mt][0] = f2tf(p[0]);
                af[mt][1] = f2tf(p[8 * SMS]);
                af[mt][2] = f2tf(p[4]);
                af[mt][3] = f2tf(p[8 * SMS + 4]);
            }
#pragma unroll
            for (int nt = 0; nt < 4; nt++) {
                const float* p = Bb + (wn * 32 + nt * 8 + g) * SMS + kk * 8 + tg;
                bf[nt][0] = f2tf(p[0]);
                bf[nt][1] = f2tf(p[4]);
            }
#pragma unroll
            for (int mt = 0; mt < 4; mt++)
#pragma unroll
                for (int nt = 0; nt < 4; nt++)
                    MMA_TF32(c[mt][nt], af[mt], bf[nt][0], bf[nt][1]);
        }
    }

#pragma unroll
    for (int mt = 0; mt < 4; mt++) {
        const int row = rowBase + wm * 64 + mt * 16 + g;
#pragma unroll
        for (int nt = 0; nt < 4; nt++) {
            const int col = colBase + wn * 32 + nt * 8 + tg * 2;
            if (Cb) {
                *(uint32_t*)&Cb[(size_t)row * N + col] =
                    pkbf(c[mt][nt][0], c[mt][nt][1]);
                *(uint32_t*)&Cb[(size_t)(row + 8) * N + col] =
                    pkbf(c[mt][nt][2], c[mt][nt][3]);
            } else {
                *(float2*)&C[(size_t)row * N + col] =
                    make_float2(c[mt][nt][0], c[mt][nt][1]);
                *(float2*)&C[(size_t)(row + 8) * N + col] =
                    make_float2(c[mt][nt][2], c[mt][nt][3]);
            }
        }
    }
}

// ---------------------------------------------------------------------------
// Features: phase -> (cos, sin) fp16 with bias + positional phase.
// ---------------------------------------------------------------------------
__global__ void feat_kernel(const float* __restrict__ phqk,
                            const float* __restrict__ bq,
                            const float* __restrict__ bk,
                            unsigned short* __restrict__ qfo,
                            unsigned short* __restrict__ kfo)
{
    int idx = blockIdx.x * blockDim.x + threadIdx.x;
    if (idx >= ROWS * NPH) return;
    int p   = idx & (NPH - 1);
    int row = idx >> 7;
    int l   = row & (LL - 1);
    int b   = row >> 11;
    int h   = p >> 3;
    int pp  = p & 7;
    int k2  = p & ~1;

    const float LC = (float)(13.287712379549449 / 128.0);
    float invf = exp2f(-(float)k2 * LC);
    float pos  = (float)l * invf;

    size_t ob = (((size_t)b * HH + h) * LL + l) * 16 + pp;
    const float* pr = phqk + (size_t)row * 256;
    float s, c;
    fastsc(pr[p] + bq[p] + pos, &s, &c);
    qfo[ob]     = f2h(c);
    qfo[ob + 8] = f2h(s);
    fastsc(pr[128 + p] + bk[p] + pos, &s, &c);
    kfo[ob]     = f2h(c);
    kfo[ob + 8] = f2h(s);
}

// ---------------------------------------------------------------------------
// Tensor-core flash attention. grid (B*H=32, 8), 128 threads (4 warps).
// S: fp16 mma m16n8k16 (features fp16, K frags via ldmatrix.x2).
// P: bf16 FA2 C->A frag reuse. PV: bf16 mma, V via ldmatrix.x4.trans.
// Fixed-max softmax (scores bounded by sqrt(8)); single streaming pass.
// ---------------------------------------------------------------------------
#define VSTR 72   // V smem row stride (bf16), conflict-free ldmatrix phases
#define KSTR 24   // K smem row stride (fp16), conflict-free ldmatrix phases
__global__ __launch_bounds__(128) void attn_tc(
    const unsigned short* __restrict__ qf, const unsigned short* __restrict__ kf,
    const unsigned short* __restrict__ Vb, float* __restrict__ Out)
{
    __shared__ __align__(16) unsigned short Ks[2][64 * KSTR];
    __shared__ __align__(16) unsigned short Vs[2][64 * VSTR];

    const int bh   = blockIdx.x;
    const int b    = bh >> 4;
    const int h    = bh & 15;
    const int tid  = threadIdx.x;
    const int warp = tid >> 5;
    const int lane = tid & 31;
    const int g    = lane >> 2, tg = lane & 3;
    const float QA = qa_const();
    const float QB = qb_const();

    const unsigned short* qfb = qf + (size_t)bh * LL * 16;
    const unsigned short* kfb = kf + (size_t)bh * LL * 16;
    const unsigned short* vgb = Vb + (size_t)b * LL * DD + h * HD;

    const uint32_t Ksu = s2u(Ks);
    const uint32_t Vsu = s2u(Vs);
    // ldmatrix lane offsets
    const uint32_t vlm = (uint32_t)((lane & 15) * VSTR + (lane >> 4) * 8) * 2u;
    const uint32_t klm = (uint32_t)((lane & 7) * KSTR + ((lane >> 3) & 1) * 8) * 2u;

    auto fill = [&](int kt, int buf) {
        const int c0 = kt * 64;
        const uint32_t kb = Ksu + (uint32_t)buf * (64 * KSTR * 2);
        {   // K tile: 64 keys x 16 fp16 = 128 x 16B chunks
            int r = tid >> 1, cc = tid & 1;
            cpa16(kb + (uint32_t)(r * KSTR + cc * 8) * 2u,
                  kfb + (size_t)(c0 + r) * 16 + cc * 8);
        }
        const uint32_t vb = Vsu + (uint32_t)buf * (64 * VSTR * 2);
#pragma unroll
        for (int u = 0; u < 4; u++) {
            int idx = tid * 4 + u;
            int r = idx >> 3, c8 = idx & 7;
            cpa16(vb + (uint32_t)(r * VSTR + c8 * 8) * 2u,
                  vgb + (size_t)(c0 + r) * DD + c8 * 8);
        }
        asm volatile("cp.async.commit_group;");
    };

#pragma unroll 1
    for (int part = 0; part < 2; part++) {
        const int qt = part ? (15 - (int)blockIdx.y) : (int)blockIdx.y;
        const int q0 = qt * 128;
        const int ntiles = 2 * qt + 2;
        const int wrow = q0 + warp * 32;          // warp's first q row

        // Q fragments (fp16, m16n8k16 A layout), rows wrow + mt*16 + {g,g+8}
        uint32_t aq[2][4];
#pragma unroll
        for (int mt = 0; mt < 2; mt++) {
            const unsigned short* qp = qfb + (size_t)(wrow + mt * 16) * 16;
            aq[mt][0] = *(const uint32_t*)&qp[(size_t)g * 16 + 2 * tg];
            aq[mt][1] = *(const uint32_t*)&qp[(size_t)(g + 8) * 16 + 2 * tg];
            aq[mt][2] = *(const uint32_t*)&qp[(size_t)g * 16 + 2 * tg + 8];
            aq[mt][3] = *(const uint32_t*)&qp[(size_t)(g + 8) * 16 + 2 * tg + 8];
        }

        float o[2][8][4] = {};
        float ls[2][2]   = {};

        fill(0, 0);
#pragma unroll 1
        for (int kt = 0; kt < ntiles; kt++) {
            const int buf = kt & 1;
            if (kt + 1 < ntiles) {
                fill(kt + 1, buf ^ 1);
                asm volatile("cp.async.wait_group 1;");
            } else {
                asm volatile("cp.async.wait_group 0;");
            }
            __syncthreads();

            const int c0 = kt * 64;
            if (c0 <= wrow + 31) {                      // not fully masked
                const bool domask = (c0 + 63 > wrow);
                const uint32_t kbase = Ksu + (uint32_t)buf * (64 * KSTR * 2) + klm;
                const uint32_t vbase = Vsu + (uint32_t)buf * (64 * VSTR * 2) + vlm;

#pragma unroll
                for (int mt = 0; mt < 2; mt++) {
                    // ---- S = Qf Kf^T (fp16 k16) ----
                    float s[8][4] = {};
#pragma unroll
                    for (int nd = 0; nd < 8; nd++) {
                        uint32_t kb0, kb1;
                        LDSM_X2(kb0, kb1, kbase + (uint32_t)(nd * 8 * KSTR) * 2u);
                        MMA_F16(s[nd], aq[mt], kb0, kb1);
                    }
                    // ---- softmax (fixed max) + pack P to bf16 A-frags ----
                    const int row0 = wrow + mt * 16 + g;
                    uint32_t pk[16];
#pragma unroll
                    for (int nd = 0; nd < 8; nd++) {
                        const int col = c0 + nd * 8 + 2 * tg;
                        float p0 = exp2f(fmaf(s[nd][0], QA, -QB));
                        float p1 = exp2f(fmaf(s[nd][1], QA, -QB));
                        float p2 = exp2f(fmaf(s[nd][2], QA, -QB));
                        float p3 = exp2f(fmaf(s[nd][3], QA, -QB));
                        if (domask) {
                            if (col > row0)         p0 = 0.f;
                            if (col + 1 > row0)     p1 = 0.f;
                            if (col > row0 + 8)     p2 = 0.f;
                            if (col + 1 > row0 + 8) p3 = 0.f;
                        }
                        ls[mt][0] += p0 + p1;
                        ls[mt][1] += p2 + p3;
                        pk[2 * nd]     = pkbf(p0, p1);
                        pk[2 * nd + 1] = pkbf(p2, p3);
                    }
                    // ---- O += P V (bf16) ----
#pragma unroll
                    for (int kv = 0; kv < 4; kv++) {
                        const uint32_t* a = &pk[4 * kv];
#pragma unroll
                        for (int np = 0; np < 4; np++) {
                            uint32_t r0, r1, r2, r3;
                            LDSM_T4(r0, r1, r2, r3,
                                    vbase + (uint32_t)(kv * 16 * VSTR + np * 16) * 2u);
                            MMA_BF16(o[mt][2 * np],     a, r0, r1);
                            MMA_BF16(o[mt][2 * np + 1], a, r2, r3);
                        }
                    }
                }
            }
            __syncthreads();
        }

        // quad-reduce row sums
#pragma unroll
        for (int mt = 0; mt < 2; mt++)
#pragma unroll
            for (int r = 0; r < 2; r++) {
                float v = ls[mt][r];
                v += __shfl_xor_sync(0xffffffffu, v, 1);
                v += __shfl_xor_sync(0xffffffffu, v, 2);
                ls[mt][r] = 1.0f / v;
            }

#pragma unroll
        for (int mt = 0; mt < 2; mt++) {
            const int row = wrow + mt * 16 + g;
            const float i0 = ls[mt][0], i1 = ls[mt][1];
#pragma unroll
            for (int nd = 0; nd < 8; nd++) {
                const int col = h * HD + nd * 8 + 2 * tg;
                *(float2*)&Out[(size_t)(b * LL + row) * DD + col] =
                    make_float2(o[mt][nd][0] * i0, o[mt][nd][1] * i0);
                *(float2*)&Out[(size_t)(b * LL + row + 8) * DD + col] =
                    make_float2(o[mt][nd][2] * i1, o[mt][nd][3] * i1);
            }
        }
    }
}

// ---------------------------------------------------------------------------
// Residual + LayerNorm
// ---------------------------------------------------------------------------
__global__ __launch_bounds__(256) void ln_kernel(
    const float* __restrict__ xr, const float* __restrict__ pj,
    const float* __restrict__ gamma, const float* __restrict__ beta,
    float* __restrict__ out)
{
    __shared__ float rs[8], rss[8];
    const int row = blockIdx.x;
    const int t   = threadIdx.x;

    const float4* xv = (const float4*)(xr + (size_t)row * DD);
    const float4* pv = (const float4*)(pj + (size_t)row * DD);
    float4 a = xv[t], c = pv[t];
    float h0 = a.x + c.x, h1 = a.y + c.y, h2 = a.z + c.z, h3 = a.w + c.w;
    float s  = h0 + h1 + h2 + h3;
    float ss = h0 * h0 + h1 * h1 + h2 * h2 + h3 * h3;
#pragma unroll
    for (int o = 16; o > 0; o >>= 1) {
        s  += __shfl_down_sync(0xffffffffu, s,  o);
        ss += __shfl_down_sync(0xffffffffu, ss, o);
    }
    if ((t & 31) == 0) { rs[t >> 5] = s; rss[t >> 5] = ss; }
    __syncthreads();
    float st = 0.f, sst = 0.f;
#pragma unroll
    for (int w = 0; w < 8; w++) { st += rs[w]; sst += rss[w]; }
    const float mu  = st * (1.0f / DD);
    const float var = sst * (1.0f / DD) - mu * mu;
    const float inv = rsqrtf(var + 1e-5f);

    float4 g  = ((const float4*)gamma)[t];
    float4 be = ((const float4*)beta)[t];
    float4 o4 = make_float4((h0 - mu) * inv * g.x + be.x,
                            (h1 - mu) * inv * g.y + be.y,
                            (h2 - mu) * inv * g.z + be.z,
                            (h3 - mu) * inv * g.w + be.w);
    ((float4*)(out + (size_t)row * DD))[t] = o4;
}

// ---------------------------------------------------------------------------
// Launch
// ---------------------------------------------------------------------------
extern "C" void kernel_launch(void* const* d_in, const int* in_sizes, int n_in,
                              void* d_out, int out_size)
{
    const float* x_real = (const float*)d_in[0];
    const float* x_imag = (const float*)d_in[1];
    const float* Wq     = (const float*)d_in[2];
    const float* bq     = (const float*)d_in[3];
    const float* Wk     = (const float*)d_in[4];
    const float* bk     = (const float*)d_in[5];
    const float* Wv     = (const float*)d_in[6];
    const float* Wo     = (const float*)d_in[7];
    const float* gamma  = (const float*)d_in[8];
    const float* beta   = (const float*)d_in[9];
    float* out = (float*)d_out;

    float *wqk, *phqk, *aob, *pjb;
    unsigned short *qfb, *kfb, *vbf;
    cudaGetSymbolAddress((void**)&wqk,  g_wqk);
    cudaGetSymbolAddress((void**)&phqk, g_phqk);
    cudaGetSymbolAddress((void**)&qfb,  g_qf);
    cudaGetSymbolAddress((void**)&kfb,  g_kf);
    cudaGetSymbolAddress((void**)&vbf,  g_vbf);
    cudaGetSymbolAddress((void**)&aob,  g_ao);
    cudaGetSymbolAddress((void**)&pjb,  g_pj);

    cudaFuncSetAttribute(gemm_mma, cudaFuncAttributeMaxDynamicSharedMemorySize,
                         GEMM_SMEM);

    // 0) concat Wq || Wk for a single N=256 projection GEMM
    cudaMemcpyAsync(wqk, Wq, (size_t)NPH * DD * sizeof(float),
                    cudaMemcpyDeviceToDevice);
    cudaMemcpyAsync(wqk + (size_t)NPH * DD, Wk, (size_t)NPH * DD * sizeof(float),
                    cudaMemcpyDeviceToDevice);

    // 1) Q/K phase projections (tf32 tensor cores)
    gemm_mma<<<dim3(2, 32), 256, GEMM_SMEM>>>(x_imag, wqk, phqk, nullptr, 256, DD);
    // 2) cos/sin features (fp16 out, fast sincos)
    feat_kernel<<<(ROWS * NPH) / 256, 256>>>(phqk, bq, bk, qfb, kfb);
    // 3) V projection -> bf16 output
    gemm_mma<<<dim3(8, 32), 256, GEMM_SMEM>>>(x_real, Wv, nullptr, vbf, DD, DD);
    // 4) tensor-core flash attention
    attn_tc<<<dim3(BB * HH, 8), 128>>>(qfb, kfb, vbf, aob);
    // 5) output projection
    gemm_mma<<<dim3(8, 32), 256, GEMM_SMEM>>>(aob, Wo, pjb, nullptr, DD, DD);
    // 6) residual + LayerNorm
    ln_kernel<<<ROWS, 256>>>(x_real, pjb, gamma, beta, out);
    // 7) second output = x_imag passthrough
    cudaMemcpyAsync(out + (size_t)ROWS * DD, x_imag,
                    (size_t)ROWS * DD * sizeof(float),
                    cudaMemcpyDeviceToDevice);
}